// round 4
// baseline (speedup 1.0000x reference)
#include <cuda_runtime.h>
#include <math.h>

#define DM      128
#define HID     256
#define NN      17
#define ND      32
#define NODEF   (NN*ND)      // 544
#define M_MAX   65536

// Scratch (no cudaMalloc allowed) -------------------------------------------
__device__ float g_h[M_MAX * HID];         // [M,256] hidden after GELU
__device__ float g_nodes[M_MAX * NODEF];   // [M,544] node features
__device__ float g_adjS1[NN * NN];
__device__ float g_adjS2[NN * NN];

__device__ __forceinline__ float gelu_erf(float x) {
    // exact (erf) GELU, matching jax.nn.gelu(approximate=False)
    return 0.5f * x * (1.0f + erff(x * 0.70710678118654752440f));
}

// ---------------------------------------------------------------------------
// adj softmax precompute: rows 0..16 -> adj1, 17..33 -> adj2
// ---------------------------------------------------------------------------
__global__ void adj_softmax_kernel(const float* __restrict__ a1,
                                   const float* __restrict__ a2) {
    int t = threadIdx.x;
    const float* src;
    float* dst;
    int r;
    if (t < NN)           { src = a1; dst = g_adjS1; r = t; }
    else if (t < 2 * NN)  { src = a2; dst = g_adjS2; r = t - NN; }
    else return;

    const float* row = src + r * NN;
    float m = -3.0e38f;
    #pragma unroll
    for (int j = 0; j < NN; j++) m = fmaxf(m, row[j]);
    float e[NN];
    float s = 0.0f;
    #pragma unroll
    for (int j = 0; j < NN; j++) { e[j] = expf(row[j] - m); s += e[j]; }
    float inv = 1.0f / s;
    #pragma unroll
    for (int j = 0; j < NN; j++) dst[r * NN + j] = e[j] * inv;
}

// ---------------------------------------------------------------------------
// Register-tiled SGEMM: C[M,N] = op(A[M,K] @ B[K,N] + bias[N])
// BM=128, BN=128, BK=8, 256 threads, 8x8 per-thread microtile.
// Requires M % 128 == 0, K % 8 == 0, N % 4 == 0 (N guarded).
// ---------------------------------------------------------------------------
template <bool DO_GELU>
__global__ __launch_bounds__(256)
void sgemm_bias_kernel(const float* __restrict__ A,
                       const float* __restrict__ B,
                       const float* __restrict__ bias,
                       float* __restrict__ C,
                       int M, int N, int K) {
    constexpr int BM = 128, BN = 128, BK = 8, TM = 8, TN = 8;
    __shared__ float As[BK][BM];
    __shared__ float Bs[BK][BN];

    const int tid = threadIdx.x;
    const int bm = blockIdx.y * BM;
    const int bn = blockIdx.x * BN;

    const int tx = tid & 15;        // 16 cols of threads (each covers 8 N)
    const int ty = tid >> 4;        // 16 rows of threads (each covers 8 M)

    // A load: one float4 per thread: row = tid>>1 (0..127), col = (tid&1)*4
    const int aRow = tid >> 1;
    const int aCol = (tid & 1) * 4;
    // B load: one float4 per thread: row = tid>>5 (0..7), col = (tid&31)*4
    const int bRow = tid >> 5;
    const int bCol = (tid & 31) * 4;

    float acc[TM][TN];
    #pragma unroll
    for (int i = 0; i < TM; i++)
        #pragma unroll
        for (int j = 0; j < TN; j++) acc[i][j] = 0.0f;

    for (int k0 = 0; k0 < K; k0 += BK) {
        float4 av = *reinterpret_cast<const float4*>(
            &A[(size_t)(bm + aRow) * K + k0 + aCol]);
        As[aCol + 0][aRow] = av.x;
        As[aCol + 1][aRow] = av.y;
        As[aCol + 2][aRow] = av.z;
        As[aCol + 3][aRow] = av.w;

        float4 bv = make_float4(0.f, 0.f, 0.f, 0.f);
        if (bn + bCol < N)   // N % 4 == 0 and bCol % 4 == 0 -> whole float4 valid
            bv = *reinterpret_cast<const float4*>(
                &B[(size_t)(k0 + bRow) * N + bn + bCol]);
        *reinterpret_cast<float4*>(&Bs[bRow][bCol]) = bv;

        __syncthreads();

        #pragma unroll
        for (int kk = 0; kk < BK; kk++) {
            float a[TM], b[TN];
            float4 a0 = *reinterpret_cast<const float4*>(&As[kk][ty * TM]);
            float4 a1 = *reinterpret_cast<const float4*>(&As[kk][ty * TM + 4]);
            a[0] = a0.x; a[1] = a0.y; a[2] = a0.z; a[3] = a0.w;
            a[4] = a1.x; a[5] = a1.y; a[6] = a1.z; a[7] = a1.w;
            float4 b0 = *reinterpret_cast<const float4*>(&Bs[kk][tx * TN]);
            float4 b1 = *reinterpret_cast<const float4*>(&Bs[kk][tx * TN + 4]);
            b[0] = b0.x; b[1] = b0.y; b[2] = b0.z; b[3] = b0.w;
            b[4] = b1.x; b[5] = b1.y; b[6] = b1.z; b[7] = b1.w;
            #pragma unroll
            for (int i = 0; i < TM; i++)
                #pragma unroll
                for (int j = 0; j < TN; j++)
                    acc[i][j] = fmaf(a[i], b[j], acc[i][j]);
        }
        __syncthreads();
    }

    #pragma unroll
    for (int i = 0; i < TM; i++) {
        const int row = bm + ty * TM + i;
        #pragma unroll
        for (int j = 0; j < TN; j++) {
            const int col = bn + tx * TN + j;
            if (col < N) {
                float v = acc[i][j] + bias[col];
                if (DO_GELU) v = gelu_erf(v);
                C[(size_t)row * N + col] = v;
            }
        }
    }
}

// ---------------------------------------------------------------------------
// Fused GAT1 -> GAT2 -> coord projection.
// 544 threads = 17 warps; warp i handles joint i, lane f handles feature f.
// ---------------------------------------------------------------------------
__global__ __launch_bounds__(544)
void gat_fused_kernel(const float* __restrict__ nodes_in,
                      const float* __restrict__ Wg1, const float* __restrict__ bg1,
                      const float* __restrict__ Wg2, const float* __restrict__ bg2,
                      const float* __restrict__ Wc,  const float* __restrict__ bc,
                      float* __restrict__ out,
                      int ntok, int tok_per_block) {
    __shared__ float sW1[ND][ND];
    __shared__ float sW2[ND][ND];
    __shared__ float sA1[NN][NN];
    __shared__ float sA2[NN][NN];
    __shared__ float sbg1[ND], sbg2[ND];
    __shared__ float sWc0[ND], sWc1[ND];
    __shared__ float sbc[2];
    __shared__ float sN[NN][ND];
    __shared__ float sMix[NN][ND];

    const int tid = threadIdx.x;

    for (int idx = tid; idx < ND * ND; idx += blockDim.x) {
        sW1[idx / ND][idx % ND] = Wg1[idx];
        sW2[idx / ND][idx % ND] = Wg2[idx];
    }
    for (int idx = tid; idx < NN * NN; idx += blockDim.x) {
        sA1[idx / NN][idx % NN] = g_adjS1[idx];
        sA2[idx / NN][idx % NN] = g_adjS2[idx];
    }
    if (tid < ND) {
        sbg1[tid] = bg1[tid];
        sbg2[tid] = bg2[tid];
        sWc0[tid] = Wc[tid * 2 + 0];
        sWc1[tid] = Wc[tid * 2 + 1];
    }
    if (tid < 2) sbc[tid] = bc[tid];
    __syncthreads();

    const int i = tid >> 5;   // joint (0..16)
    const int f = tid & 31;   // feature (0..31)

    const int t0 = blockIdx.x * tok_per_block;
    const int t1 = min(t0 + tok_per_block, ntok);

    for (int t = t0; t < t1; t++) {
        const float n = nodes_in[(size_t)t * NODEF + i * ND + f];
        sN[i][f] = n;
        __syncthreads();

        // --- GAT1: graph mix ---
        float mix = 0.0f;
        #pragma unroll
        for (int j = 0; j < NN; j++) mix = fmaf(sA1[i][j], sN[j][f], mix);
        sMix[i][f] = mix;
        __syncthreads();

        float lin = sbg1[f];
        #pragma unroll
        for (int k = 0; k < ND; k++) lin = fmaf(sMix[i][k], sW1[k][f], lin);
        const float v1 = gelu_erf(lin) + n;
        __syncthreads();                 // done reading sN / sMix

        sN[i][f] = v1;
        __syncthreads();

        // --- GAT2 ---
        mix = 0.0f;
        #pragma unroll
        for (int j = 0; j < NN; j++) mix = fmaf(sA2[i][j], sN[j][f], mix);
        sMix[i][f] = mix;
        __syncthreads();

        lin = sbg2[f];
        #pragma unroll
        for (int k = 0; k < ND; k++) lin = fmaf(sMix[i][k], sW2[k][f], lin);
        const float v2 = gelu_erf(lin) + v1;

        // --- coord projection: per-warp reduction over the 32 features ---
        float p0 = v2 * sWc0[f];
        float p1 = v2 * sWc1[f];
        #pragma unroll
        for (int off = 16; off > 0; off >>= 1) {
            p0 += __shfl_down_sync(0xffffffffu, p0, off);
            p1 += __shfl_down_sync(0xffffffffu, p1, off);
        }
        if (f == 0) {
            out[(size_t)t * (NN * 2) + i * 2 + 0] = p0 + sbc[0];
            out[(size_t)t * (NN * 2) + i * 2 + 1] = p1 + sbc[1];
        }
        __syncthreads();                 // before next token reuses sN / sMix
    }
}

// ---------------------------------------------------------------------------
extern "C" void kernel_launch(void* const* d_in, const int* in_sizes, int n_in,
                              void* d_out, int out_size) {
    const float* x    = (const float*)d_in[0];
    const float* W1   = (const float*)d_in[1];
    const float* b1   = (const float*)d_in[2];
    const float* W2   = (const float*)d_in[3];
    const float* b2   = (const float*)d_in[4];
    const float* adj1 = (const float*)d_in[5];
    const float* Wg1  = (const float*)d_in[6];
    const float* bg1  = (const float*)d_in[7];
    const float* adj2 = (const float*)d_in[8];
    const float* Wg2  = (const float*)d_in[9];
    const float* bg2  = (const float*)d_in[10];
    const float* Wc   = (const float*)d_in[11];
    const float* bc   = (const float*)d_in[12];
    float* out = (float*)d_out;

    const int M = in_sizes[0] / DM;   // 65536 for the reference shapes

    float *hbuf, *nbuf;
    cudaGetSymbolAddress((void**)&hbuf, g_h);
    cudaGetSymbolAddress((void**)&nbuf, g_nodes);

    // 1. adjacency softmax (tiny)
    adj_softmax_kernel<<<1, 64>>>(adj1, adj2);

    // 2. h = gelu(x @ W1 + b1)
    {
        dim3 grid(HID / 128, M / 128);
        sgemm_bias_kernel<true><<<grid, 256>>>(x, W1, b1, hbuf, M, HID, DM);
    }

    // 3. nodes = h @ W2 + b2
    {
        dim3 grid((NODEF + 127) / 128, M / 128);
        sgemm_bias_kernel<false><<<grid, 256>>>(hbuf, W2, b2, nbuf, M, NODEF, HID);
    }

    // 4. fused GAT1 -> GAT2 -> coord head
    {
        const int nblk = 2048;
        const int tpb = (M + nblk - 1) / nblk;
        gat_fused_kernel<<<nblk, 544>>>(nbuf, Wg1, bg1, Wg2, bg2, Wc, bc,
                                        out, M, tpb);
    }
}